// round 4
// baseline (speedup 1.0000x reference)
#include <cuda_runtime.h>
#include <cuda_bf16.h>
#include <string.h>
#include <math.h>

// ---------------- problem constants ----------------
#define EID   30000
#define EMB   256
#define HID   512
#define IN_DIM 3
#define SRC_T 128
#define TRG_T 50
#define B     64
#define G3    (3*HID)          // 1536

// ---------------- device state ----------------
__device__ float g_hT[2 * HID * B];                    // transposed hidden [k][b], double buffered
__device__ float g_giEnc[(size_t)SRC_T * B * G3];      // encoder gi precomputed (incl. b_ih)
__device__ float g_A[8 * B * G3];                      // gh partials
__device__ float g_Bp[5 * B * G3];                     // gi partials (decoder)
__device__ float g_C[12 * B * HID];                    // r1 partials
__device__ float g_logits[B * EID];
__device__ float g_xdec[(EMB + 1) * B];                // transposed decoder input [k][b]
__device__ float g_xcat[(EMB + HID) * B];              // transposed concat(emb_mt, h)
__device__ float g_rate[B];
__device__ int   g_idx[B];

// ---------------- packed fp32 FMA (sm_100+) ----------------
__device__ __forceinline__ float2 ffma2(float2 a, float2 b, float2 c) {
    unsigned long long ua, ub, uc, ud;
    memcpy(&ua, &a, 8); memcpy(&ub, &b, 8); memcpy(&uc, &c, 8);
    asm("fma.rn.f32x2 %0, %1, %2, %3;" : "=l"(ud) : "l"(ua), "l"(ub), "l"(uc));
    float2 d; memcpy(&d, &ud, 8); return d;
}

// ---------------- generic batch-64 GEMM ----------------
// out[(blockIdx.y*64 + b)*N + n] = sum_{k in chunk} XT[k][b] * W[n][k]  (+ bias[n] if given)
// XT: [K][64] transposed activations. W: [N][ldW] row-major. KT=64 internal k-tiles.
#define KT 64

template<int JT, int NTH>
__launch_bounds__(NTH)
__global__ void gemm64k(const float* __restrict__ XT, const float* __restrict__ W,
                        const float* __restrict__ bias, float* __restrict__ out,
                        int N, int ldW, int K, int kChunk)
{
    __shared__ float xs[KT * 66];          // [k][b] padded: stride 66 keeps LDS.64 aligned, no bank conflicts
    __shared__ float ws[JT * (KT + 1)];    // [n_local][k] padded

    const int tid = threadIdx.x;
    const int n0  = blockIdx.x * JT;
    const int kb  = blockIdx.y * kChunk;
    const int ke  = min(K, kb + kChunk);
    const int bpg = tid & 7;               // batch-pair group (8)
    const int cg  = tid >> 3;              // column group; cols = cg*4 .. cg*4+3

    float2 acc[4][4];
    #pragma unroll
    for (int i = 0; i < 4; i++)
        #pragma unroll
        for (int c = 0; c < 4; c++) acc[i][c] = make_float2(0.f, 0.f);

    for (int kt = kb; kt < ke; kt += KT) {
        const int kn = min(KT, ke - kt);
        __syncthreads();
        // stage X tile (coalesced: consecutive threads -> consecutive b)
        for (int e = tid; e < kn * 64; e += NTH) {
            int k = e >> 6, b = e & 63;
            xs[k * 66 + b] = XT[(kt + k) * 64 + b];
        }
        // stage W tile
        if (kn == KT) {
            for (int e = tid; e < JT * KT; e += NTH) {
                int nl = e >> 6, k = e & 63;
                int n = n0 + nl;
                ws[nl * (KT + 1) + k] = (n < N) ? W[(size_t)n * ldW + kt + k] : 0.f;
            }
        } else {
            for (int e = tid; e < JT * kn; e += NTH) {
                int nl = e / kn, k = e - nl * kn;
                int n = n0 + nl;
                ws[nl * (KT + 1) + k] = (n < N) ? W[(size_t)n * ldW + kt + k] : 0.f;
            }
        }
        __syncthreads();

        #pragma unroll 4
        for (int k = 0; k < kn; k++) {
            float2 xv[4];
            #pragma unroll
            for (int i = 0; i < 4; i++)
                xv[i] = *reinterpret_cast<const float2*>(&xs[k * 66 + 2 * (bpg + 8 * i)]);
            #pragma unroll
            for (int c = 0; c < 4; c++) {
                float wv = ws[(cg * 4 + c) * (KT + 1) + k];
                float2 wp = make_float2(wv, wv);
                #pragma unroll
                for (int i = 0; i < 4; i++)
                    acc[i][c] = ffma2(xv[i], wp, acc[i][c]);
            }
        }
    }

    float* o = out + (size_t)blockIdx.y * 64 * N;
    #pragma unroll
    for (int c = 0; c < 4; c++) {
        int n = n0 + cg * 4 + c;
        if (n >= N) continue;
        float bv = bias ? bias[n] : 0.f;
        #pragma unroll
        for (int i = 0; i < 4; i++) {
            int p = bpg + 8 * i;
            o[(size_t)(2 * p)     * N + n] = acc[i][c].x + bv;
            o[(size_t)(2 * p + 1) * N + n] = acc[i][c].y + bv;
        }
    }
}

// ---------------- GRU gate combine ----------------
// nB==0: Bsrc points to precomputed gi (bias already included). Else Bsrc = nB partial chunks + b_ih.
__global__ void gru_combine(const float* __restrict__ Ap, int nA,
                            const float* __restrict__ Bsrc, int nB,
                            const float* __restrict__ b_ih, const float* __restrict__ b_hh,
                            const float* __restrict__ hin, float* __restrict__ hout,
                            const int* __restrict__ src_len, int t)
{
    int i = blockIdx.x * blockDim.x + threadIdx.x;
    if (i >= B * HID) return;
    int b = i >> 9, j = i & (HID - 1);

    float ar = b_hh[j], az = b_hh[j + HID], an = b_hh[j + 2 * HID];
    for (int p = 0; p < nA; p++) {
        const float* base = Ap + (size_t)p * B * G3 + (size_t)b * G3;
        ar += base[j]; az += base[j + HID]; an += base[j + 2 * HID];
    }
    float br, bz, bn;
    if (nB == 0) {
        const float* base = Bsrc + (size_t)b * G3;
        br = base[j]; bz = base[j + HID]; bn = base[j + 2 * HID];
    } else {
        br = b_ih[j]; bz = b_ih[j + HID]; bn = b_ih[j + 2 * HID];
        for (int p = 0; p < nB; p++) {
            const float* base = Bsrc + (size_t)p * B * G3 + (size_t)b * G3;
            br += base[j]; bz += base[j + HID]; bn += base[j + 2 * HID];
        }
    }
    float r = 1.f / (1.f + expf(-(ar + br)));
    float z = 1.f / (1.f + expf(-(az + bz)));
    float n = tanhf(bn + r * an);
    float ho = hin[j * 64 + b];
    float hn = (1.f - z) * n + z * ho;
    if (src_len && !(t < src_len[b])) hn = ho;
    hout[j * 64 + b] = hn;
}

// ---------------- fused log-softmax + first-argmax + output write ----------------
__global__ void softmax_argmax(const float* __restrict__ logits, float* __restrict__ out,
                               int row, int* __restrict__ idxout)
{
    const int b = blockIdx.x, tid = threadIdx.x;
    const int T = 1024;
    const float* L = logits + (size_t)b * EID;
    __shared__ float sv[1024];
    __shared__ int   si[1024];

    float mx = -3.4e38f; int ix = 0x7fffffff;
    for (int n = tid; n < EID; n += T) {
        float v = L[n];
        if (v > mx) { mx = v; ix = n; }
    }
    sv[tid] = mx; __syncthreads();
    for (int s = 512; s; s >>= 1) { if (tid < s) sv[tid] = fmaxf(sv[tid], sv[tid + s]); __syncthreads(); }
    float gm = sv[0]; __syncthreads();
    si[tid] = (mx == gm) ? ix : 0x7fffffff; __syncthreads();
    for (int s = 512; s; s >>= 1) { if (tid < s) si[tid] = min(si[tid], si[tid + s]); __syncthreads(); }
    int amax = si[0]; __syncthreads();

    float acc = 0.f;
    for (int n = tid; n < EID; n += T) acc += expf(L[n] - gm);
    sv[tid] = acc; __syncthreads();
    for (int s = 512; s; s >>= 1) { if (tid < s) sv[tid] += sv[tid + s]; __syncthreads(); }
    float lse = gm + logf(sv[0]);

    float* O = out + ((size_t)row * B + b) * EID;
    for (int n = tid; n < EID; n += T) O[n] = L[n] - lse;
    if (tid == 0) idxout[b] = amax;
}

// ---------------- rate head finish ----------------
__global__ void rate_head(const float* __restrict__ C, const float* __restrict__ b_r1,
                          const float* __restrict__ W_r2, const float* __restrict__ b_r2,
                          float* __restrict__ outRate, int row, float* __restrict__ rateState)
{
    const int b = blockIdx.x, j = threadIdx.x;  // 512 threads
    float v = b_r1[j];
    for (int p = 0; p < 12; p++) v += C[((size_t)p * B + b) * HID + j];
    v = fmaxf(v, 0.f) * W_r2[j];
    __shared__ float sv[512];
    sv[j] = v; __syncthreads();
    for (int s = 256; s; s >>= 1) { if (j < s) sv[j] += sv[j + s]; __syncthreads(); }
    if (j == 0) {
        float pr = 1.f / (1.f + expf(-(sv[0] + b_r2[0])));
        outRate[(size_t)row * B + b] = pr;
        rateState[b] = pr;
    }
}

// ---------------- input builders ----------------
__global__ void build_xdec(const float* __restrict__ emb_dec, const int* __restrict__ idx,
                           const float* __restrict__ rate, float* __restrict__ xT)
{
    int i = blockIdx.x * 256 + threadIdx.x;
    if (i >= (EMB + 1) * 64) return;
    int k = i >> 6, b = i & 63;
    xT[i] = (k < EMB) ? emb_dec[(size_t)idx[b] * EMB + k] : rate[b];
}

__global__ void build_xcat(const float* __restrict__ emb_mt, const int* __restrict__ idx,
                           const float* __restrict__ hT, float* __restrict__ xT)
{
    int i = blockIdx.x * 256 + threadIdx.x;
    if (i >= (EMB + HID) * 64) return;
    int k = i >> 6, b = i & 63;
    xT[i] = (k < EMB) ? emb_mt[(size_t)idx[b] * EMB + k] : hT[i - EMB * 64];
}

__global__ void init_state(float* __restrict__ hT0, int* __restrict__ idx, float* __restrict__ rate,
                           const int* __restrict__ trg_eid, const float* __restrict__ trg_rate)
{
    int i = blockIdx.x * 256 + threadIdx.x;
    if (i < HID * B) hT0[i] = 0.f;
    if (i < B) { idx[i] = trg_eid[i]; rate[i] = trg_rate[i]; }
}

// encoder gi precompute: out[tb*1536 + j] = b_ih[j] + sum_{k<3} src[tb][k]*W_ih[j][k]
__global__ void enc_gi(const float* __restrict__ src, const float* __restrict__ W_ih,
                       const float* __restrict__ b_ih, float* __restrict__ out)
{
    int j = blockIdx.x * 256 + threadIdx.x;   // < 1536
    int tb = blockIdx.y;                       // < 128*64
    const float* x = src + (size_t)tb * 3;
    out[(size_t)tb * G3 + j] = b_ih[j] + x[0] * W_ih[j * 3] + x[1] * W_ih[j * 3 + 1]
                                       + x[2] * W_ih[j * 3 + 2];
}

// ---------------- host launcher ----------------
extern "C" void kernel_launch(void* const* d_in, const int* in_sizes, int n_in,
                              void* d_out, int out_size)
{
    const float* src      = (const float*)d_in[0];
    const int*   src_len  = (const int*)  d_in[1];
    const int*   trg_eid  = (const int*)  d_in[2];
    const float* trg_rate = (const float*)d_in[3];
    const float* W_ih_enc = (const float*)d_in[4];
    const float* W_hh_enc = (const float*)d_in[5];
    const float* b_ih_enc = (const float*)d_in[6];
    const float* b_hh_enc = (const float*)d_in[7];
    const float* emb_dec  = (const float*)d_in[8];
    const float* W_ih_dec = (const float*)d_in[9];
    const float* W_hh_dec = (const float*)d_in[10];
    const float* b_ih_dec = (const float*)d_in[11];
    const float* b_hh_dec = (const float*)d_in[12];
    const float* emb_mt   = (const float*)d_in[13];
    const float* W_eid    = (const float*)d_in[14];
    const float* b_eid    = (const float*)d_in[15];
    const float* W_r1     = (const float*)d_in[16];
    const float* b_r1     = (const float*)d_in[17];
    const float* W_r2     = (const float*)d_in[18];
    const float* b_r2     = (const float*)d_in[19];
    float* out = (float*)d_out;
    float* out_rate = out + (size_t)TRG_T * B * EID;

    float *hT, *giEnc, *A, *Bp, *C, *logits, *xdec, *xcat, *rate;
    int* idx;
    cudaGetSymbolAddress((void**)&hT,     g_hT);
    cudaGetSymbolAddress((void**)&giEnc,  g_giEnc);
    cudaGetSymbolAddress((void**)&A,      g_A);
    cudaGetSymbolAddress((void**)&Bp,     g_Bp);
    cudaGetSymbolAddress((void**)&C,      g_C);
    cudaGetSymbolAddress((void**)&logits, g_logits);
    cudaGetSymbolAddress((void**)&xdec,   g_xdec);
    cudaGetSymbolAddress((void**)&xcat,   g_xcat);
    cudaGetSymbolAddress((void**)&rate,   g_rate);
    cudaGetSymbolAddress((void**)&idx,    g_idx);
    float* hbuf[2] = { hT, hT + HID * B };

    // zero output row 0 (eid + rate)
    cudaMemsetAsync(out, 0, (size_t)B * EID * sizeof(float), 0);
    cudaMemsetAsync(out_rate, 0, B * sizeof(float), 0);

    init_state<<<128, 256>>>(hbuf[0], idx, rate, trg_eid, trg_rate);
    enc_gi<<<dim3(6, SRC_T * B), 256>>>(src, W_ih_enc, b_ih_enc, giEnc);

    // ---------- encoder: 128 masked GRU steps ----------
    for (int t = 0; t < SRC_T; t++) {
        gemm64k<64, 128><<<dim3(24, 8), 128>>>(hbuf[t & 1], W_hh_enc, nullptr, A,
                                               G3, HID, HID, 64);
        gru_combine<<<128, 256>>>(A, 8, giEnc + (size_t)t * B * G3, 0,
                                  nullptr, b_hh_enc, hbuf[t & 1], hbuf[(t + 1) & 1],
                                  src_len, t);
    }

    // ---------- decoder: 49 autoregressive steps ----------
    for (int s = 0; s < TRG_T - 1; s++) {
        const int pi = s & 1, po = (s + 1) & 1;
        build_xdec<<<65, 256>>>(emb_dec, idx, rate, xdec);
        gemm64k<64, 128><<<dim3(24, 5), 128>>>(xdec, W_ih_dec, nullptr, Bp,
                                               G3, EMB + 1, EMB + 1, 64);
        gemm64k<64, 128><<<dim3(24, 8), 128>>>(hbuf[pi], W_hh_dec, nullptr, A,
                                               G3, HID, HID, 64);
        gru_combine<<<128, 256>>>(A, 8, Bp, 5, b_ih_dec, b_hh_dec,
                                  hbuf[pi], hbuf[po], nullptr, 0);
        // big output projection (fp32, FFMA2-packed): [64,512] x [512,30000]
        gemm64k<96, 192><<<dim3(313, 1), 192>>>(hbuf[po], W_eid, b_eid, logits,
                                                EID, HID, HID, HID);
        softmax_argmax<<<64, 1024>>>(logits, out, s + 1, idx);
        build_xcat<<<192, 256>>>(emb_mt, idx, hbuf[po], xcat);
        gemm64k<64, 128><<<dim3(8, 12), 128>>>(xcat, W_r1, nullptr, C,
                                               HID, EMB + HID, EMB + HID, 64);
        rate_head<<<64, 512>>>(C, b_r1, W_r2, b_r2, out_rate, s + 1, rate);
    }
}